// round 1
// baseline (speedup 1.0000x reference)
#include <cuda_runtime.h>

#define H      256
#define NMAX   8192
#define NCLS   6       // classes 1..6 participate in confused pairs
#define TA     32      // anchors per block
#define TB     128     // columns per tile
#define KC     16      // K-chunk for B staging
#define SPLIT  4       // column-dimension block split for parallelism

// ---- scratch (static device globals; no dynamic allocation) ----
__device__ float    g_e[NMAX * H];       // normalized embeddings (8 MB, L2-resident)
__device__ int      g_idx[NCLS][NMAX];   // per-class compacted row indices
__device__ int      g_cnt[NCLS];
__device__ unsigned g_posmin[NMAX];      // monotone-encoded float min
__device__ unsigned g_negmax[NMAX];      // monotone-encoded float max
__device__ float    g_trip[NMAX];
__device__ int      g_flag[NMAX];
__device__ int      g_lab64;             // 1 if labels are int64, 0 if int32

// monotone float<->uint mapping so atomicMin/atomicMax on unsigned == float min/max
__device__ __forceinline__ unsigned enc_f(float f) {
    unsigned u = __float_as_uint(f);
    return (u & 0x80000000u) ? ~u : (u | 0x80000000u);
}
__device__ __forceinline__ float dec_f(unsigned v) {
    return __uint_as_float((v & 0x80000000u) ? (v ^ 0x80000000u) : ~v);
}

// ---- K0: zero per-class counters ----
__global__ void k_zero() {
    if (threadIdx.x < NCLS) g_cnt[threadIdx.x] = 0;
}

// ---- K0b: detect label dtype (int64 vs int32) ----
__global__ void k_detect(const long long* __restrict__ lab, int N) {
    if (threadIdx.x == 0 && blockIdx.x == 0) {
        int n = (N < 16) ? N : 16;
        int ok = 1;
        for (int i = 0; i < n; i++) {
            long long v = lab[i];
            if (v < -1000000LL || v > 1000000LL) ok = 0;
        }
        g_lab64 = ok;
    }
}

// ---- K1: L2-normalize rows (warp per row) + init per-row scratch ----
__global__ void k_norm(const float* __restrict__ emb, int N) {
    int row  = blockIdx.x * 8 + (threadIdx.x >> 5);
    int lane = threadIdx.x & 31;
    if (row >= N) return;
    const float4* src = reinterpret_cast<const float4*>(emb) + row * (H / 4);
    float4 v0 = src[lane * 2];
    float4 v1 = src[lane * 2 + 1];
    float ss = v0.x*v0.x + v0.y*v0.y + v0.z*v0.z + v0.w*v0.w
             + v1.x*v1.x + v1.y*v1.y + v1.z*v1.z + v1.w*v1.w;
#pragma unroll
    for (int o = 16; o; o >>= 1) ss += __shfl_xor_sync(0xffffffffu, ss, o);
    float s = 1.0f / fmaxf(sqrtf(ss), 1e-12f);
    float4* dst = reinterpret_cast<float4*>(g_e) + row * (H / 4);
    v0.x *= s; v0.y *= s; v0.z *= s; v0.w *= s;
    v1.x *= s; v1.y *= s; v1.z *= s; v1.w *= s;
    dst[lane * 2]     = v0;
    dst[lane * 2 + 1] = v1;
    if (lane == 0) {
        g_posmin[row] = enc_f(1e9f);
        g_negmax[row] = enc_f(-1e9f);
        g_trip[row]   = 0.0f;
        g_flag[row]   = 0;
    }
}

// ---- K2: compact row indices per class 1..6 ----
__global__ void k_compact(const void* __restrict__ labv, int N) {
    int i = blockIdx.x * 256 + threadIdx.x;
    if (i >= N) return;
    long long l = g_lab64 ? reinterpret_cast<const long long*>(labv)[i]
                          : (long long)reinterpret_cast<const int*>(labv)[i];
    if (l >= 1 && l <= 6) {
        int c = (int)l - 1;          // class index 0..5; confused pair is c^1
        int p = atomicAdd(&g_cnt[c], 1);
        g_idx[c][p] = i;
    }
}

// ---- K3: main fused GEMM + row min/max ----
// grid = (ceil(NMAX/TA), NCLS, SPLIT); block = 256 threads (8 warps)
// Each block: 32 anchors of class c, loops over column tiles (stride SPLIT) of
// class c (phase 0: hardest positive, min, self-excluded) and class c^1
// (phase 1: hardest negative, max). 4x4 register micro-tile per thread.
__global__ __launch_bounds__(256) void k_main() {
    __shared__ float As[H][TA];     // 32 KB, k-major (anchor vectors, full depth)
    __shared__ float Bs[KC][TB];    // 8 KB, k-major chunk of column vectors
    __shared__ int   sAidx[TA];
    __shared__ int   sBidx[TB];

    int c = blockIdx.y;
    int z = blockIdx.z;
    int cntA = g_cnt[c];
    int a0 = blockIdx.x * TA;
    if (a0 >= cntA) return;

    int tid = threadIdx.x;
    int tx  = tid & 31;   // column group (4 cols each)
    int ty  = tid >> 5;   // anchor group (4 anchors each); one warp per ty

    if (tid < TA) {
        int k = a0 + tid;
        sAidx[tid] = (k < cntA) ? g_idx[c][k] : -1;
    }
    __syncthreads();

    // load anchor tile transposed: As[k][a]
    {
        int a  = tid & 31;
        int q0 = tid >> 5;                // 0..7
        int gi = sAidx[a];
#pragma unroll
        for (int q = 0; q < H / 4; q += 8) {
            float4 v = (gi >= 0)
                ? reinterpret_cast<const float4*>(g_e)[gi * (H / 4) + q + q0]
                : make_float4(0.f, 0.f, 0.f, 0.f);
            int k = (q + q0) * 4;
            As[k + 0][a] = v.x; As[k + 1][a] = v.y;
            As[k + 2][a] = v.z; As[k + 3][a] = v.w;
        }
    }

    float minP[4], maxN[4];
#pragma unroll
    for (int i = 0; i < 4; i++) { minP[i] = 1e9f; maxN[i] = -1e9f; }

#pragma unroll
    for (int phase = 0; phase < 2; phase++) {
        int lc   = (phase == 0) ? c : (c ^ 1);
        int cntB = g_cnt[lc];
        int ntiles = (cntB + TB - 1) / TB;
        for (int t = z; t < ntiles; t += SPLIT) {
            __syncthreads();   // protect sBidx/Bs against previous tile's readers
            if (tid < TB) {
                int j = t * TB + tid;
                sBidx[tid] = (j < cntB) ? g_idx[lc][j] : -1;
            }
            float acc[4][4];
#pragma unroll
            for (int i = 0; i < 4; i++)
#pragma unroll
                for (int j = 0; j < 4; j++) acc[i][j] = 0.0f;

            for (int kc = 0; kc < H; kc += KC) {
                __syncthreads();   // Bs consumed / sBidx visible
                {
                    int j  = tid & 127;
                    int qq = tid >> 7;            // 0..1
                    int gj = sBidx[j];
#pragma unroll
                    for (int r = 0; r < 2; r++) {
                        int kq = qq + r * 2;      // 0..3 (KC/4 quads)
                        float4 v = (gj >= 0)
                            ? reinterpret_cast<const float4*>(g_e)[gj * (H / 4) + (kc >> 2) + kq]
                            : make_float4(0.f, 0.f, 0.f, 0.f);
                        int k = kq * 4;
                        Bs[k + 0][j] = v.x; Bs[k + 1][j] = v.y;
                        Bs[k + 2][j] = v.z; Bs[k + 3][j] = v.w;
                    }
                }
                __syncthreads();
#pragma unroll
                for (int k = 0; k < KC; k++) {
                    float4 a4 = *reinterpret_cast<const float4*>(&As[kc + k][ty * 4]);
                    float4 b4 = *reinterpret_cast<const float4*>(&Bs[k][tx * 4]);
                    acc[0][0] += a4.x * b4.x; acc[0][1] += a4.x * b4.y;
                    acc[0][2] += a4.x * b4.z; acc[0][3] += a4.x * b4.w;
                    acc[1][0] += a4.y * b4.x; acc[1][1] += a4.y * b4.y;
                    acc[1][2] += a4.y * b4.z; acc[1][3] += a4.y * b4.w;
                    acc[2][0] += a4.z * b4.x; acc[2][1] += a4.z * b4.y;
                    acc[2][2] += a4.z * b4.z; acc[2][3] += a4.z * b4.w;
                    acc[3][0] += a4.w * b4.x; acc[3][1] += a4.w * b4.y;
                    acc[3][2] += a4.w * b4.z; acc[3][3] += a4.w * b4.w;
                }
            }
            // fold this tile into running min/max
#pragma unroll
            for (int bi = 0; bi < 4; bi++) {
                int gj = sBidx[tx * 4 + bi];
                if (gj < 0) continue;
#pragma unroll
                for (int ai = 0; ai < 4; ai++) {
                    float v = acc[ai][bi];
                    if (phase == 0) {
                        if (gj != sAidx[ty * 4 + ai])
                            minP[ai] = fminf(minP[ai], v);
                    } else {
                        maxN[ai] = fmaxf(maxN[ai], v);
                    }
                }
            }
        }
    }

    // warp-level reduction: all 32 lanes of warp ty share the same 4 anchors
#pragma unroll
    for (int i = 0; i < 4; i++) {
#pragma unroll
        for (int o = 16; o; o >>= 1) {
            minP[i] = fminf(minP[i], __shfl_xor_sync(0xffffffffu, minP[i], o));
            maxN[i] = fmaxf(maxN[i], __shfl_xor_sync(0xffffffffu, maxN[i], o));
        }
    }
    if (tx == 0) {
#pragma unroll
        for (int i = 0; i < 4; i++) {
            int gi = sAidx[ty * 4 + i];
            if (gi >= 0) {
                atomicMin(&g_posmin[gi], enc_f(minP[i]));
                atomicMax(&g_negmax[gi], enc_f(maxN[i]));
            }
        }
    }
}

// ---- K4: per-anchor triplet value ----
__global__ void k_finalize(const void* __restrict__ labv, int N) {
    int i = blockIdx.x * 256 + threadIdx.x;
    if (i >= N) return;
    long long l = g_lab64 ? reinterpret_cast<const long long*>(labv)[i]
                          : (long long)reinterpret_cast<const int*>(labv)[i];
    if (l < 1 || l > 6) return;
    int c = (int)l - 1;
    if (g_cnt[c] >= 2 && g_cnt[c ^ 1] >= 1) {
        float hp = dec_f(g_posmin[i]);
        float hn = dec_f(g_negmax[i]);
        g_trip[i] = fmaxf(0.0f, 0.5f + hn - hp);
        g_flag[i] = 1;
    }
}

// ---- K5: deterministic reduction to the scalar loss ----
__global__ void k_reduce(float* __restrict__ out, int N) {
    __shared__ float ssum[256];
    __shared__ int   scnt[256];
    int tid = threadIdx.x;
    float s = 0.0f;
    int cn = 0;
    for (int i = tid; i < N; i += 256) { s += g_trip[i]; cn += g_flag[i]; }
    ssum[tid] = s; scnt[tid] = cn;
    __syncthreads();
    for (int o = 128; o; o >>= 1) {
        if (tid < o) { ssum[tid] += ssum[tid + o]; scnt[tid] += scnt[tid + o]; }
        __syncthreads();
    }
    if (tid == 0) out[0] = (scnt[0] > 0) ? ssum[0] / (float)scnt[0] : 0.0f;
}

extern "C" void kernel_launch(void* const* d_in, const int* in_sizes, int n_in,
                              void* d_out, int out_size) {
    const float* emb = (const float*)d_in[0];
    const void*  lab = d_in[1];
    int N = in_sizes[1];
    if (N > NMAX) N = NMAX;

    k_zero<<<1, 32>>>();
    k_detect<<<1, 32>>>((const long long*)lab, N);
    k_norm<<<(N + 7) / 8, 256>>>(emb, N);
    k_compact<<<(N + 255) / 256, 256>>>(lab, N);

    dim3 grid((NMAX + TA - 1) / TA, NCLS, SPLIT);
    k_main<<<grid, 256>>>();

    k_finalize<<<(N + 255) / 256, 256>>>(lab, N);
    k_reduce<<<1, 256>>>((float*)d_out, N);
}

// round 2
// speedup vs baseline: 1.5733x; 1.5733x over previous
#include <cuda_runtime.h>

#define H    256
#define HQ   (H/4)
#define NMAX 8192
#define NCLS 6       // classes 1..6 participate in confused pairs; pair of c is c^1 (0-based)
#define TA   64      // anchors per job tile
#define TB   128     // columns per job tile
#define KC   16      // K chunk staged in shared

// ---- scratch (static device globals; no dynamic allocation) ----
__device__ __align__(16) float g_e[NMAX * H];   // normalized embeddings (8 MB)
__device__ int      g_idx[NCLS][NMAX];          // per-class compacted row indices
__device__ int      g_cnt[NCLS];
__device__ unsigned g_posmin[NMAX];             // monotone-encoded float min
__device__ unsigned g_negmax[NMAX];             // monotone-encoded float max
__device__ int      g_lab64;                    // labels are int64 (1) or int32 (0)
__device__ int      g_ticket;                   // persistent-kernel job counter

// monotone float<->uint map: atomicMin/Max on unsigned == float min/max
__device__ __forceinline__ unsigned enc_f(float f) {
    unsigned u = __float_as_uint(f);
    return (u & 0x80000000u) ? ~u : (u | 0x80000000u);
}
__device__ __forceinline__ float dec_f(unsigned v) {
    return __uint_as_float((v & 0x80000000u) ? (v ^ 0x80000000u) : ~v);
}

// packed f32x2 helpers
#define FMA2(d, a, b, c) \
    asm("fma.rn.f32x2 %0, %1, %2, %3;" : "=l"(d) : "l"(a), "l"(b), "l"(c))
#define PACKDUP(d, f) \
    asm("mov.b64 %0, {%1, %1};" : "=l"(d) : "r"(__float_as_uint(f)))
#define UNPACK2(lo, hi, v) \
    asm("mov.b64 {%0, %1}, %2;" : "=r"(lo), "=r"(hi) : "l"(v))

// ---- K0: zero counters + ticket, detect label dtype ----
__global__ void k_zero(const long long* __restrict__ lab, int N) {
    int t = threadIdx.x;
    if (t < NCLS) g_cnt[t] = 0;
    if (t == 30) g_ticket = 0;
    if (t == 31) {
        int n = (N < 16) ? N : 16;
        int ok = 1;
        for (int i = 0; i < n; i++) {
            long long v = lab[i];
            if (v < -1000000LL || v > 1000000LL) ok = 0;
        }
        g_lab64 = ok;
    }
}

// ---- K1: L2-normalize rows (warp per row) + init per-row min/max ----
__global__ void k_norm(const float* __restrict__ emb, int N) {
    int row  = blockIdx.x * 8 + (threadIdx.x >> 5);
    int lane = threadIdx.x & 31;
    if (row >= N) return;
    const float4* src = reinterpret_cast<const float4*>(emb) + row * HQ;
    float4 v0 = src[lane * 2];
    float4 v1 = src[lane * 2 + 1];
    float ss = v0.x*v0.x + v0.y*v0.y + v0.z*v0.z + v0.w*v0.w
             + v1.x*v1.x + v1.y*v1.y + v1.z*v1.z + v1.w*v1.w;
#pragma unroll
    for (int o = 16; o; o >>= 1) ss += __shfl_xor_sync(0xffffffffu, ss, o);
    float s = 1.0f / fmaxf(sqrtf(ss), 1e-12f);
    float4* dst = reinterpret_cast<float4*>(g_e) + row * HQ;
    v0.x *= s; v0.y *= s; v0.z *= s; v0.w *= s;
    v1.x *= s; v1.y *= s; v1.z *= s; v1.w *= s;
    dst[lane * 2]     = v0;
    dst[lane * 2 + 1] = v1;
    if (lane == 0) {
        g_posmin[row] = enc_f(1e9f);
        g_negmax[row] = enc_f(-1e9f);
    }
}

// ---- K2: compact row indices per class 1..6 ----
__global__ void k_compact(const void* __restrict__ labv, int N) {
    int i = blockIdx.x * 256 + threadIdx.x;
    if (i >= N) return;
    long long l = g_lab64 ? reinterpret_cast<const long long*>(labv)[i]
                          : (long long)reinterpret_cast<const int*>(labv)[i];
    if (l >= 1 && l <= 6) {
        int c = (int)l - 1;
        int p = atomicAdd(&g_cnt[c], 1);
        g_idx[c][p] = i;
    }
}

// ---- K3: persistent fused GEMM + hardest-pos/neg fold ----
// Job = (class c, anchor tile of TA, col tile of TB over pos-list then neg-list).
// 256 threads: warp ty owns 8 anchors (ty*8..), lane tx owns 4 cols (tx*4..).
// Inner product via packed fma.rn.f32x2: A read as natural anchor-pairs,
// B duplicated per scalar. 16 FFMA2 = 64 MACs per thread per k-step.
__global__ __launch_bounds__(256, 2) void k_main() {
    __shared__ __align__(16) float As[H][TA];   // 64 KB, k-major
    __shared__ __align__(16) float Bs[KC][TB];  // 8 KB, k-major chunk
    __shared__ int sA[TA];
    __shared__ int sB[TB];
    __shared__ int sjob;
    __shared__ int scnt[NCLS];

    int tid = threadIdx.x;
    int tx  = tid & 31;
    int ty  = tid >> 5;
    if (tid < NCLS) scnt[tid] = g_cnt[tid];

    for (;;) {
        if (tid == 0) sjob = atomicAdd(&g_ticket, 1);
        __syncthreads();                 // also covers scnt on first pass
        int rem = sjob;

        int c = -1, atile = 0, ct = 0, pt = 0;
#pragma unroll
        for (int cc = 0; cc < NCLS; cc++) {
            int at = (scnt[cc] + TA - 1) / TA;
            int p  = (scnt[cc] + TB - 1) / TB;
            int n  = (scnt[cc ^ 1] + TB - 1) / TB;
            int nj = at * (p + n);
            if (c < 0) {
                if (rem < nj) { c = cc; atile = rem / (p + n); ct = rem % (p + n); pt = p; }
                else rem -= nj;
            }
        }
        if (c < 0) break;

        bool isPos = (ct < pt);
        int lc     = isPos ? c : (c ^ 1);
        int cbase  = (isPos ? ct : ct - pt) * TB;
        int cntA = scnt[c], cntB = scnt[lc];

        if (tid < TA) { int a = atile * TA + tid; sA[tid] = (a < cntA) ? g_idx[c][a] : -1; }
        if (tid < TB) { int j = cbase + tid;      sB[tid] = (j < cntB) ? g_idx[lc][j] : -1; }
        __syncthreads();

        // stage anchor tile transposed: As[k][a]
        {
            int a  = tid & 63;
            int q0 = tid >> 6;           // 0..3
            int gi = sA[a];
#pragma unroll
            for (int q = q0; q < HQ; q += 4) {
                float4 v = (gi >= 0)
                    ? reinterpret_cast<const float4*>(g_e)[gi * HQ + q]
                    : make_float4(0.f, 0.f, 0.f, 0.f);
                int k = q * 4;
                As[k + 0][a] = v.x; As[k + 1][a] = v.y;
                As[k + 2][a] = v.z; As[k + 3][a] = v.w;
            }
        }

        unsigned long long acc[4][4];   // [anchor-pair][col], each = f32x2 over 2 anchors
#pragma unroll
        for (int p = 0; p < 4; p++)
#pragma unroll
            for (int j = 0; j < 4; j++) acc[p][j] = 0ull;

        for (int kc = 0; kc < H; kc += KC) {
            __syncthreads();             // Bs consumed by previous chunk (and As staged, 1st iter)
            {
                int j  = tid & 127;
                int qq = tid >> 7;       // 0..1
                int gj = sB[j];
#pragma unroll
                for (int r = 0; r < 2; r++) {
                    int kq = qq + r * 2; // 0..3
                    float4 v = (gj >= 0)
                        ? reinterpret_cast<const float4*>(g_e)[gj * HQ + (kc >> 2) + kq]
                        : make_float4(0.f, 0.f, 0.f, 0.f);
                    int k = kq * 4;
                    Bs[k + 0][j] = v.x; Bs[k + 1][j] = v.y;
                    Bs[k + 2][j] = v.z; Bs[k + 3][j] = v.w;
                }
            }
            __syncthreads();
#pragma unroll
            for (int k = 0; k < KC; k++) {
                const ulonglong2* apv =
                    reinterpret_cast<const ulonglong2*>(&As[kc + k][ty * 8]);
                ulonglong2 a01 = apv[0];     // anchor pairs (0,1),(2,3)
                ulonglong2 a23 = apv[1];     // anchor pairs (4,5),(6,7)
                float4 b4 = *reinterpret_cast<const float4*>(&Bs[k][tx * 4]);
                unsigned long long bd0, bd1, bd2, bd3;
                PACKDUP(bd0, b4.x); PACKDUP(bd1, b4.y);
                PACKDUP(bd2, b4.z); PACKDUP(bd3, b4.w);
                FMA2(acc[0][0], a01.x, bd0, acc[0][0]);
                FMA2(acc[0][1], a01.x, bd1, acc[0][1]);
                FMA2(acc[0][2], a01.x, bd2, acc[0][2]);
                FMA2(acc[0][3], a01.x, bd3, acc[0][3]);
                FMA2(acc[1][0], a01.y, bd0, acc[1][0]);
                FMA2(acc[1][1], a01.y, bd1, acc[1][1]);
                FMA2(acc[1][2], a01.y, bd2, acc[1][2]);
                FMA2(acc[1][3], a01.y, bd3, acc[1][3]);
                FMA2(acc[2][0], a23.x, bd0, acc[2][0]);
                FMA2(acc[2][1], a23.x, bd1, acc[2][1]);
                FMA2(acc[2][2], a23.x, bd2, acc[2][2]);
                FMA2(acc[2][3], a23.x, bd3, acc[2][3]);
                FMA2(acc[3][0], a23.y, bd0, acc[3][0]);
                FMA2(acc[3][1], a23.y, bd1, acc[3][1]);
                FMA2(acc[3][2], a23.y, bd2, acc[3][2]);
                FMA2(acc[3][3], a23.y, bd3, acc[3][3]);
            }
        }

        // fold tile into per-anchor running min (pos) or max (neg)
        float red[8];
        int   gA[8];
#pragma unroll
        for (int i = 0; i < 8; i++) {
            red[i] = isPos ? 1e9f : -1e9f;
            gA[i]  = sA[ty * 8 + i];
        }
#pragma unroll
        for (int p = 0; p < 4; p++) {
#pragma unroll
            for (int j = 0; j < 4; j++) {
                unsigned lo, hi;
                UNPACK2(lo, hi, acc[p][j]);
                float flo = __uint_as_float(lo), fhi = __uint_as_float(hi);
                int gj = sB[tx * 4 + j];
                if (gj < 0) continue;
                if (isPos) {
                    if (gj != gA[2 * p])     red[2 * p]     = fminf(red[2 * p], flo);
                    if (gj != gA[2 * p + 1]) red[2 * p + 1] = fminf(red[2 * p + 1], fhi);
                } else {
                    red[2 * p]     = fmaxf(red[2 * p], flo);
                    red[2 * p + 1] = fmaxf(red[2 * p + 1], fhi);
                }
            }
        }
#pragma unroll
        for (int i = 0; i < 8; i++) {
#pragma unroll
            for (int o = 16; o; o >>= 1) {
                float other = __shfl_xor_sync(0xffffffffu, red[i], o);
                red[i] = isPos ? fminf(red[i], other) : fmaxf(red[i], other);
            }
        }
        if (tx == 0) {
#pragma unroll
            for (int i = 0; i < 8; i++) {
                int gi = gA[i];
                if (gi >= 0) {
                    if (isPos) atomicMin(&g_posmin[gi], enc_f(red[i]));
                    else       atomicMax(&g_negmax[gi], enc_f(red[i]));
                }
            }
        }
        // loop-top __syncthreads() guards smem reuse for the next job
    }
}

// ---- K4: per-anchor triplet + deterministic reduction to scalar loss ----
__global__ void k_finalreduce(const void* __restrict__ labv, int N,
                              float* __restrict__ out) {
    __shared__ float ssum[512];
    __shared__ int   snum[512];
    int tid = threadIdx.x;
    float s = 0.0f;
    int   n = 0;
    for (int i = tid; i < N; i += 512) {
        long long l = g_lab64 ? reinterpret_cast<const long long*>(labv)[i]
                              : (long long)reinterpret_cast<const int*>(labv)[i];
        if (l >= 1 && l <= 6) {
            int c = (int)l - 1;
            if (g_cnt[c] >= 2 && g_cnt[c ^ 1] >= 1) {
                float hp = dec_f(g_posmin[i]);
                float hn = dec_f(g_negmax[i]);
                s += fmaxf(0.0f, 0.5f + hn - hp);
                n++;
            }
        }
    }
    ssum[tid] = s; snum[tid] = n;
    __syncthreads();
    for (int o = 256; o; o >>= 1) {
        if (tid < o) { ssum[tid] += ssum[tid + o]; snum[tid] += snum[tid + o]; }
        __syncthreads();
    }
    if (tid == 0) out[0] = (snum[0] > 0) ? ssum[0] / (float)snum[0] : 0.0f;
}

extern "C" void kernel_launch(void* const* d_in, const int* in_sizes, int n_in,
                              void* d_out, int out_size) {
    const float* emb = (const float*)d_in[0];
    const void*  lab = d_in[1];
    int N = in_sizes[1];
    if (N > NMAX) N = NMAX;

    k_zero<<<1, 32>>>((const long long*)lab, N);
    k_norm<<<(N + 7) / 8, 256>>>(emb, N);
    k_compact<<<(N + 255) / 256, 256>>>(lab, N);
    k_main<<<296, 256>>>();
    k_finalreduce<<<1, 512>>>(lab, N, (float*)d_out);
}

// round 3
// speedup vs baseline: 1.6578x; 1.0537x over previous
#include <cuda_runtime.h>

#define H      256
#define HQ     (H/4)
#define NMAX   8192
#define NCLS   6       // classes 1..6; confused pair of c is c^1 (0-based)
#define TA     64      // anchors per job tile
#define TB     128     // columns per job tile
#define KC     16      // K chunk staged in shared
#define NCHUNK (H/KC)  // 16

// ---- scratch (static device globals; no dynamic allocation) ----
__device__ __align__(16) float g_e[NMAX * H];   // normalized embeddings (8 MB)
__device__ int      g_idx[NCLS][NMAX];
__device__ int      g_cnt[NCLS];
__device__ unsigned g_posmin[NMAX];
__device__ unsigned g_negmax[NMAX];
__device__ int      g_lab64;
__device__ int      g_ticket;

__device__ __forceinline__ unsigned enc_f(float f) {
    unsigned u = __float_as_uint(f);
    return (u & 0x80000000u) ? ~u : (u | 0x80000000u);
}
__device__ __forceinline__ float dec_f(unsigned v) {
    return __uint_as_float((v & 0x80000000u) ? (v ^ 0x80000000u) : ~v);
}

#define FMA2(d, a, b, c) \
    asm("fma.rn.f32x2 %0, %1, %2, %3;" : "=l"(d) : "l"(a), "l"(b), "l"(c))
#define PACKDUP(d, f) \
    asm("mov.b64 %0, {%1, %1};" : "=l"(d) : "r"(__float_as_uint(f)))
#define UNPACK2(lo, hi, v) \
    asm("mov.b64 {%0, %1}, %2;" : "=r"(lo), "=r"(hi) : "l"(v))

// ---- K0: zero counters + ticket, detect label dtype ----
__global__ void k_zero(const long long* __restrict__ lab, int N) {
    int t = threadIdx.x;
    if (t < NCLS) g_cnt[t] = 0;
    if (t == 30) g_ticket = 0;
    if (t == 31) {
        int n = (N < 16) ? N : 16;
        int ok = 1;
        for (int i = 0; i < n; i++) {
            long long v = lab[i];
            if (v < -1000000LL || v > 1000000LL) ok = 0;
        }
        g_lab64 = ok;
    }
}

// ---- K1: L2-normalize rows (warp per row) + init per-row min/max ----
__global__ void k_norm(const float* __restrict__ emb, int N) {
    int row  = blockIdx.x * 8 + (threadIdx.x >> 5);
    int lane = threadIdx.x & 31;
    if (row >= N) return;
    const float4* src = reinterpret_cast<const float4*>(emb) + row * HQ;
    float4 v0 = src[lane * 2];
    float4 v1 = src[lane * 2 + 1];
    float ss = v0.x*v0.x + v0.y*v0.y + v0.z*v0.z + v0.w*v0.w
             + v1.x*v1.x + v1.y*v1.y + v1.z*v1.z + v1.w*v1.w;
#pragma unroll
    for (int o = 16; o; o >>= 1) ss += __shfl_xor_sync(0xffffffffu, ss, o);
    float s = 1.0f / fmaxf(sqrtf(ss), 1e-12f);
    float4* dst = reinterpret_cast<float4*>(g_e) + row * HQ;
    v0.x *= s; v0.y *= s; v0.z *= s; v0.w *= s;
    v1.x *= s; v1.y *= s; v1.z *= s; v1.w *= s;
    dst[lane * 2]     = v0;
    dst[lane * 2 + 1] = v1;
    if (lane == 0) {
        g_posmin[row] = enc_f(1e9f);
        g_negmax[row] = enc_f(-1e9f);
    }
}

// ---- K2: compact row indices per class, block-aggregated atomics ----
__global__ void k_compact(const void* __restrict__ labv, int N) {
    __shared__ int hcnt[NCLS];
    __shared__ int hbase[NCLS];
    int tid = threadIdx.x;
    if (tid < NCLS) hcnt[tid] = 0;
    __syncthreads();
    int i = blockIdx.x * 256 + tid;
    int c = -1, p = 0;
    if (i < N) {
        long long l = g_lab64 ? reinterpret_cast<const long long*>(labv)[i]
                              : (long long)reinterpret_cast<const int*>(labv)[i];
        if (l >= 1 && l <= 6) {
            c = (int)l - 1;
            p = atomicAdd(&hcnt[c], 1);
        }
    }
    __syncthreads();
    if (tid < NCLS) hbase[tid] = hcnt[tid] ? atomicAdd(&g_cnt[tid], hcnt[tid]) : 0;
    __syncthreads();
    if (c >= 0) g_idx[c][hbase[c] + p] = i;
}

// ---- K3: persistent fused GEMM + hardest-pos/neg fold ----
// Job = (class c, anchor tile TA, col tile TB over pos-list or neg-list).
// Double-buffered B chunks with 2-ahead LDG prefetch; 1 barrier per chunk.
__global__ __launch_bounds__(256, 2) void k_main() {
    __shared__ __align__(16) float As[H][TA];        // 64 KB, k-major
    __shared__ __align__(16) float Bs[2][KC][TB];    // 16 KB, double-buffered
    __shared__ int sA[TA];
    __shared__ int sB[TB];
    __shared__ int sjob;
    __shared__ int scnt[NCLS];

    int tid = threadIdx.x;
    int tx  = tid & 31;
    int ty  = tid >> 5;
    if (tid < NCLS) scnt[tid] = g_cnt[tid];

    const int jb = tid & 127;        // this thread's fixed B column slot
    const int qq = tid >> 7;         // 0..1: which half of the K-chunk

    for (;;) {
        if (tid == 0) sjob = atomicAdd(&g_ticket, 1);
        __syncthreads();             // also covers scnt on first pass
        int rem = sjob;

        int c = -1, atile = 0, ct = 0, pt = 0;
#pragma unroll
        for (int cc = 0; cc < NCLS; cc++) {
            int at = (scnt[cc] + TA - 1) / TA;
            int p  = (scnt[cc] + TB - 1) / TB;
            int n  = (scnt[cc ^ 1] + TB - 1) / TB;
            int nj = at * (p + n);
            if (c < 0) {
                if (rem < nj) { c = cc; atile = rem / (p + n); ct = rem % (p + n); pt = p; }
                else rem -= nj;
            }
        }
        if (c < 0) break;

        bool isPos = (ct < pt);
        int lc     = isPos ? c : (c ^ 1);
        int cbase  = (isPos ? ct : ct - pt) * TB;
        int cntA = scnt[c], cntB = scnt[lc];

        if (tid < TA) { int a = atile * TA + tid; sA[tid] = (a < cntA) ? g_idx[c][a] : -1; }
        if (tid < TB) { int j = cbase + tid;      sB[tid] = (j < cntB) ? g_idx[lc][j] : -1; }
        __syncthreads();

        // hoist this thread's B column pointer
        int gjme = sB[jb];
        const float4* bptr = reinterpret_cast<const float4*>(g_e) + (long)(gjme < 0 ? 0 : gjme) * HQ;
        bool bvalid = (gjme >= 0);

        // stage anchor tile transposed: As[k][a] (once per job)
        {
            int a  = tid & 63;
            int q0 = tid >> 6;           // 0..3
            int gi = sA[a];
            const float4* ap = reinterpret_cast<const float4*>(g_e) + (long)(gi < 0 ? 0 : gi) * HQ;
            bool av = (gi >= 0);
#pragma unroll
            for (int q = q0; q < HQ; q += 4) {
                float4 v = av ? ap[q] : make_float4(0.f, 0.f, 0.f, 0.f);
                int k = q * 4;
                As[k + 0][a] = v.x; As[k + 1][a] = v.y;
                As[k + 2][a] = v.z; As[k + 3][a] = v.w;
            }
        }

        // prefetch chunk 0 -> regs, store to buf0, prefetch chunk 1 -> regs
        float4 pf0, pf1;
        {
            pf0 = bvalid ? bptr[qq]     : make_float4(0.f, 0.f, 0.f, 0.f);
            pf1 = bvalid ? bptr[qq + 2] : make_float4(0.f, 0.f, 0.f, 0.f);
            int k0 = qq * 4, k1 = (qq + 2) * 4;
            Bs[0][k0 + 0][jb] = pf0.x; Bs[0][k0 + 1][jb] = pf0.y;
            Bs[0][k0 + 2][jb] = pf0.z; Bs[0][k0 + 3][jb] = pf0.w;
            Bs[0][k1 + 0][jb] = pf1.x; Bs[0][k1 + 1][jb] = pf1.y;
            Bs[0][k1 + 2][jb] = pf1.z; Bs[0][k1 + 3][jb] = pf1.w;
            pf0 = bvalid ? bptr[4 + qq]     : make_float4(0.f, 0.f, 0.f, 0.f);
            pf1 = bvalid ? bptr[4 + qq + 2] : make_float4(0.f, 0.f, 0.f, 0.f);
        }
        __syncthreads();             // As staged + Bs[0] ready

        unsigned long long acc[4][4];
#pragma unroll
        for (int p = 0; p < 4; p++)
#pragma unroll
            for (int j = 0; j < 4; j++) acc[p][j] = 0ull;

#pragma unroll 1
        for (int t = 0; t < NCHUNK; t++) {
            const float (*bsc)[TB] = Bs[t & 1];
            const int kcb = t * KC;
            // store prefetched chunk t+1, then issue LDG for chunk t+2
            if (t + 1 < NCHUNK) {
                float (*bsn)[TB] = Bs[(t + 1) & 1];
                int k0 = qq * 4, k1 = (qq + 2) * 4;
                bsn[k0 + 0][jb] = pf0.x; bsn[k0 + 1][jb] = pf0.y;
                bsn[k0 + 2][jb] = pf0.z; bsn[k0 + 3][jb] = pf0.w;
                bsn[k1 + 0][jb] = pf1.x; bsn[k1 + 1][jb] = pf1.y;
                bsn[k1 + 2][jb] = pf1.z; bsn[k1 + 3][jb] = pf1.w;
                if (t + 2 < NCHUNK) {
                    int qbase = (t + 2) * (KC / 4);
                    pf0 = bvalid ? bptr[qbase + qq]     : make_float4(0.f, 0.f, 0.f, 0.f);
                    pf1 = bvalid ? bptr[qbase + qq + 2] : make_float4(0.f, 0.f, 0.f, 0.f);
                }
            }
#pragma unroll
            for (int k = 0; k < KC; k++) {
                const ulonglong2* apv =
                    reinterpret_cast<const ulonglong2*>(&As[kcb + k][ty * 8]);
                ulonglong2 a01 = apv[0];
                ulonglong2 a23 = apv[1];
                float4 b4 = *reinterpret_cast<const float4*>(&bsc[k][tx * 4]);
                unsigned long long bd0, bd1, bd2, bd3;
                PACKDUP(bd0, b4.x); PACKDUP(bd1, b4.y);
                PACKDUP(bd2, b4.z); PACKDUP(bd3, b4.w);
                FMA2(acc[0][0], a01.x, bd0, acc[0][0]);
                FMA2(acc[0][1], a01.x, bd1, acc[0][1]);
                FMA2(acc[0][2], a01.x, bd2, acc[0][2]);
                FMA2(acc[0][3], a01.x, bd3, acc[0][3]);
                FMA2(acc[1][0], a01.y, bd0, acc[1][0]);
                FMA2(acc[1][1], a01.y, bd1, acc[1][1]);
                FMA2(acc[1][2], a01.y, bd2, acc[1][2]);
                FMA2(acc[1][3], a01.y, bd3, acc[1][3]);
                FMA2(acc[2][0], a23.x, bd0, acc[2][0]);
                FMA2(acc[2][1], a23.x, bd1, acc[2][1]);
                FMA2(acc[2][2], a23.x, bd2, acc[2][2]);
                FMA2(acc[2][3], a23.x, bd3, acc[2][3]);
                FMA2(acc[3][0], a23.y, bd0, acc[3][0]);
                FMA2(acc[3][1], a23.y, bd1, acc[3][1]);
                FMA2(acc[3][2], a23.y, bd2, acc[3][2]);
                FMA2(acc[3][3], a23.y, bd3, acc[3][3]);
            }
            __syncthreads();
        }

        // fold tile into per-anchor running min (pos) / max (neg)
        float red[8];
        int   gA[8];
#pragma unroll
        for (int i = 0; i < 8; i++) {
            red[i] = isPos ? 1e9f : -1e9f;
            gA[i]  = sA[ty * 8 + i];
        }
#pragma unroll
        for (int p = 0; p < 4; p++) {
#pragma unroll
            for (int j = 0; j < 4; j++) {
                unsigned lo, hi;
                UNPACK2(lo, hi, acc[p][j]);
                float flo = __uint_as_float(lo), fhi = __uint_as_float(hi);
                int gj = sB[tx * 4 + j];
                if (gj < 0) continue;
                if (isPos) {
                    if (gj != gA[2 * p])     red[2 * p]     = fminf(red[2 * p], flo);
                    if (gj != gA[2 * p + 1]) red[2 * p + 1] = fminf(red[2 * p + 1], fhi);
                } else {
                    red[2 * p]     = fmaxf(red[2 * p], flo);
                    red[2 * p + 1] = fmaxf(red[2 * p + 1], fhi);
                }
            }
        }
#pragma unroll
        for (int i = 0; i < 8; i++) {
#pragma unroll
            for (int o = 16; o; o >>= 1) {
                float other = __shfl_xor_sync(0xffffffffu, red[i], o);
                red[i] = isPos ? fminf(red[i], other) : fmaxf(red[i], other);
            }
        }
        if (tx == 0) {
#pragma unroll
            for (int i = 0; i < 8; i++) {
                int gi = gA[i];
                if (gi >= 0) {
                    if (isPos) atomicMin(&g_posmin[gi], enc_f(red[i]));
                    else       atomicMax(&g_negmax[gi], enc_f(red[i]));
                }
            }
        }
        __syncthreads();             // protect sA/sB/As/Bs before next job
    }
}

// ---- K4: per-anchor triplet + deterministic reduction ----
__global__ void k_finalreduce(const void* __restrict__ labv, int N,
                              float* __restrict__ out) {
    __shared__ float ssum[512];
    __shared__ int   snum[512];
    int tid = threadIdx.x;
    float s = 0.0f;
    int   n = 0;
    for (int i = tid; i < N; i += 512) {
        long long l = g_lab64 ? reinterpret_cast<const long long*>(labv)[i]
                              : (long long)reinterpret_cast<const int*>(labv)[i];
        if (l >= 1 && l <= 6) {
            int c = (int)l - 1;
            if (g_cnt[c] >= 2 && g_cnt[c ^ 1] >= 1) {
                float hp = dec_f(g_posmin[i]);
                float hn = dec_f(g_negmax[i]);
                s += fmaxf(0.0f, 0.5f + hn - hp);
                n++;
            }
        }
    }
    ssum[tid] = s; snum[tid] = n;
    __syncthreads();
    for (int o = 256; o; o >>= 1) {
        if (tid < o) { ssum[tid] += ssum[tid + o]; snum[tid] += snum[tid + o]; }
        __syncthreads();
    }
    if (tid == 0) out[0] = (snum[0] > 0) ? ssum[0] / (float)snum[0] : 0.0f;
}

extern "C" void kernel_launch(void* const* d_in, const int* in_sizes, int n_in,
                              void* d_out, int out_size) {
    const float* emb = (const float*)d_in[0];
    const void*  lab = d_in[1];
    int N = in_sizes[1];
    if (N > NMAX) N = NMAX;

    k_zero<<<1, 32>>>((const long long*)lab, N);
    k_norm<<<(N + 7) / 8, 256>>>(emb, N);
    k_compact<<<(N + 255) / 256, 256>>>(lab, N);
    k_main<<<296, 256>>>();
    k_finalreduce<<<1, 512>>>(lab, N, (float*)d_out);
}

// round 6
// speedup vs baseline: 1.9036x; 1.1483x over previous
#include <cuda_runtime.h>
#include <cuda_bf16.h>
#include <cstdint>

#define H      256
#define NMAX   8192
#define NCLS   6        // classes 1..6; confused pair of c is c^1 (0-based)
#define TAJ    128      // anchors per job (M)
#define TBJ    128      // cols per job (N)
#define KCH    128      // K elements per staged chunk
#define TILE_B 32768    // bytes per staged matrix per chunk: 128 rows x 128 bf16 x 2B
#define DSMEM  (4 * TILE_B + 1024)

// ---- scratch (static device globals; no dynamic allocation) ----
__device__ __nv_bfloat16 g_eh[NMAX * H];   // hi bf16 of normalized embeddings
__device__ __nv_bfloat16 g_el[NMAX * H];   // lo residual bf16
__device__ int      g_idx[NCLS][NMAX];
__device__ int      g_cnt[NCLS];
__device__ unsigned g_posmin[NMAX];
__device__ unsigned g_negmax[NMAX];
__device__ int      g_lab64;
__device__ int      g_ticket;

__device__ __forceinline__ unsigned enc_f(float f) {
    unsigned u = __float_as_uint(f);
    return (u & 0x80000000u) ? ~u : (u | 0x80000000u);
}
__device__ __forceinline__ float dec_f(unsigned v) {
    return __uint_as_float((v & 0x80000000u) ? (v ^ 0x80000000u) : ~v);
}
__device__ __forceinline__ uint32_t smem_u32(const void* p) {
    uint32_t a;
    asm("{ .reg .u64 t; cvta.to.shared.u64 t, %1; cvt.u32.u64 %0, t; }" : "=r"(a) : "l"(p));
    return a;
}

#define LDSM_X4(r0, r1, r2, r3, addr) \
    asm volatile("ldmatrix.sync.aligned.m8n8.x4.shared.b16 {%0,%1,%2,%3}, [%4];" \
        : "=r"(r0), "=r"(r1), "=r"(r2), "=r"(r3) : "r"(addr))

#define MMA16816(d, a, b) \
    asm volatile("mma.sync.aligned.m16n8k16.row.col.f32.bf16.bf16.f32 " \
        "{%0,%1,%2,%3}, {%4,%5,%6,%7}, {%8,%9}, {%0,%1,%2,%3};" \
        : "+f"((d)[0]), "+f"((d)[1]), "+f"((d)[2]), "+f"((d)[3]) \
        : "r"((a)[0]), "r"((a)[1]), "r"((a)[2]), "r"((a)[3]), \
          "r"((b)[0]), "r"((b)[1]))

// ---- K0: zero counters + ticket, detect label dtype ----
__global__ void k_zero(const long long* __restrict__ lab, int N) {
    int t = threadIdx.x;
    if (t < NCLS) g_cnt[t] = 0;
    if (t == 30) g_ticket = 0;
    if (t == 31) {
        int n = (N < 16) ? N : 16;
        int ok = 1;
        for (int i = 0; i < n; i++) {
            long long v = lab[i];
            if (v < -1000000LL || v > 1000000LL) ok = 0;
        }
        g_lab64 = ok;
    }
}

// ---- K1: L2-normalize rows, emit bf16 hi/lo split, init min/max ----
__global__ void k_norm(const float* __restrict__ emb, int N) {
    int row  = blockIdx.x * 8 + (threadIdx.x >> 5);
    int lane = threadIdx.x & 31;
    if (row >= N) return;
    const float4* src = reinterpret_cast<const float4*>(emb) + row * (H / 4);
    float4 v0 = src[lane * 2];
    float4 v1 = src[lane * 2 + 1];
    float ss = v0.x*v0.x + v0.y*v0.y + v0.z*v0.z + v0.w*v0.w
             + v1.x*v1.x + v1.y*v1.y + v1.z*v1.z + v1.w*v1.w;
#pragma unroll
    for (int o = 16; o; o >>= 1) ss += __shfl_xor_sync(0xffffffffu, ss, o);
    float s = 1.0f / fmaxf(sqrtf(ss), 1e-12f);
    float f[8] = { v0.x*s, v0.y*s, v0.z*s, v0.w*s, v1.x*s, v1.y*s, v1.z*s, v1.w*s };
    unsigned hw[4], lw[4];
#pragma unroll
    for (int p = 0; p < 4; p++) {
        float a = f[2*p], b = f[2*p+1];
        __nv_bfloat16 ha = __float2bfloat16_rn(a);
        __nv_bfloat16 hb = __float2bfloat16_rn(b);
        __nv_bfloat16 la = __float2bfloat16_rn(a - __bfloat162float(ha));
        __nv_bfloat16 lb = __float2bfloat16_rn(b - __bfloat162float(hb));
        hw[p] = (unsigned)__bfloat16_as_ushort(ha) | ((unsigned)__bfloat16_as_ushort(hb) << 16);
        lw[p] = (unsigned)__bfloat16_as_ushort(la) | ((unsigned)__bfloat16_as_ushort(lb) << 16);
    }
    reinterpret_cast<uint4*>(g_eh)[row * (H / 8) + lane] = make_uint4(hw[0], hw[1], hw[2], hw[3]);
    reinterpret_cast<uint4*>(g_el)[row * (H / 8) + lane] = make_uint4(lw[0], lw[1], lw[2], lw[3]);
    if (lane == 0) {
        g_posmin[row] = enc_f(1e9f);
        g_negmax[row] = enc_f(-1e9f);
    }
}

// ---- K2: compact row indices per class, block-aggregated atomics ----
__global__ void k_compact(const void* __restrict__ labv, int N) {
    __shared__ int hcnt[NCLS];
    __shared__ int hbase[NCLS];
    int tid = threadIdx.x;
    if (tid < NCLS) hcnt[tid] = 0;
    __syncthreads();
    int i = blockIdx.x * 256 + tid;
    int c = -1, p = 0;
    if (i < N) {
        long long l = g_lab64 ? reinterpret_cast<const long long*>(labv)[i]
                              : (long long)reinterpret_cast<const int*>(labv)[i];
        if (l >= 1 && l <= 6) {
            c = (int)l - 1;
            p = atomicAdd(&hcnt[c], 1);
        }
    }
    __syncthreads();
    if (tid < NCLS) hbase[tid] = hcnt[tid] ? atomicAdd(&g_cnt[tid], hcnt[tid]) : 0;
    __syncthreads();
    if (c >= 0) g_idx[c][hbase[c] + p] = i;
}

// ---- K3: persistent HMMA (mma.sync bf16 hi/lo) GEMM + hardest fold ----
// Job = (class c, 128-anchor tile, 128-col tile, pos-list or neg-list).
// K processed in 2 chunks of 128: per chunk stage Ah/Al/Bh/Bl (32 KB each,
// XOR-swizzled), then 8 k16-steps of 48 mma.sync per warp (3 split passes,
// 4x4 16x8 tiles). Accumulators persist across chunks.
__global__ __launch_bounds__(256, 1) void k_main() {
    extern __shared__ char dsm_raw[];
    __shared__ int sA[TAJ], sB[TBJ];
    __shared__ int sjob, scnt[NCLS];

    int tid  = threadIdx.x;
    int wid  = tid >> 5;
    int lane = tid & 31;
    int wm   = wid >> 2;          // 0..1  (M: 64 rows each)
    int wn   = wid & 3;           // 0..3  (N: 32 cols each)

    unsigned dynaddr = smem_u32(dsm_raw);
    unsigned base0   = (dynaddr + 1023u) & ~1023u;

    if (tid < NCLS) scnt[tid] = g_cnt[tid];

    // per-lane ldmatrix address components
    const uint32_t aRow = ((lane >> 3) & 1) * 8 + (lane & 7);
    const uint32_t kAh  = ((lane >> 4) & 1) * 16;
    const uint32_t bRow = ((lane >> 4) & 1) * 8 + (lane & 7);
    const uint32_t kBh  = ((lane >> 3) & 1) * 16;
    const uint32_t xm   = (lane & 7) << 4;
    const uint32_t aByte = (wm * 64 + aRow) * 128;
    const uint32_t bByte = (wn * 32 + bRow) * 128;

    const uint32_t bAh = base0;
    const uint32_t bAl = base0 + TILE_B;
    const uint32_t bBh = base0 + 2 * TILE_B;
    const uint32_t bBl = base0 + 3 * TILE_B;

    for (;;) {
        if (tid == 0) sjob = atomicAdd(&g_ticket, 1);
        __syncthreads();
        int rem = sjob;

        int c = -1, atile = 0, ct = 0, pt = 0;
#pragma unroll
        for (int cc = 0; cc < NCLS; cc++) {
            int at = (scnt[cc] + TAJ - 1) / TAJ;
            int p  = (scnt[cc] + TBJ - 1) / TBJ;
            int n  = (scnt[cc ^ 1] + TBJ - 1) / TBJ;
            int nj = at * (p + n);
            if (c < 0) {
                if (rem < nj) { c = cc; atile = rem / (p + n); ct = rem % (p + n); pt = p; }
                else rem -= nj;
            }
        }
        if (c < 0) break;

        bool isPos = (ct < pt);
        int lc     = isPos ? c : (c ^ 1);
        int cbase  = (isPos ? ct : ct - pt) * TBJ;
        int cntA = scnt[c], cntB = scnt[lc];

        if (tid < TAJ) { int a = atile * TAJ + tid; sA[tid] = (a < cntA) ? g_idx[c][a]  : -1; }
        else { int j = cbase + (tid - TAJ); sB[tid - TAJ] = (j < cntB) ? g_idx[lc][j] : -1; }
        __syncthreads();

        float acc[4][4][4];
#pragma unroll
        for (int mt = 0; mt < 4; mt++)
#pragma unroll
            for (int nt = 0; nt < 4; nt++)
#pragma unroll
                for (int e = 0; e < 4; e++) acc[mt][nt][e] = 0.0f;

#pragma unroll 1
        for (int ch = 0; ch < 2; ch++) {
            int kc = ch * KCH;
            // ---- stage 4 matrices for this K-chunk (Ah, Al, Bh, Bl) ----
            // unit = 16 bytes; 16 units per row per matrix; 8192 units total.
            for (int u = tid; u < 4 * 128 * 16; u += 256) {
                int i  = u & 15;            // 16B unit within chunk row
                int gr = u >> 4;            // 0..511
                int m  = gr >> 7;           // matrix 0..3
                int r  = gr & 127;          // row
                int s  = i >> 3;            // k-subtile 0..1
                int li = i & 7;
                int g  = (m < 2) ? sA[r] : sB[r];
                const __nv_bfloat16* src = (m & 1) ? g_el : g_eh;
                uint4 v = make_uint4(0, 0, 0, 0);
                if (g >= 0)
                    v = reinterpret_cast<const uint4*>(src + (size_t)g * H + kc)[i];
                unsigned dst = base0 + m * TILE_B + s * 16384 + r * 128
                             + ((unsigned)(li * 16) ^ (((unsigned)r & 7) << 4));
                asm volatile("st.shared.v4.b32 [%0], {%1,%2,%3,%4};"
                             :: "r"(dst), "r"(v.x), "r"(v.y), "r"(v.z), "r"(v.w));
            }
            __syncthreads();

            // ---- compute: 8 k16 steps, 3 passes, 4x4 tiles per warp ----
#pragma unroll 1
            for (int kk = 0; kk < 8; kk++) {
                uint32_t sOff = (uint32_t)(kk >> 2) * 16384;
                uint32_t kbl  = (uint32_t)(kk & 3) * 32;
                uint32_t koA  = (kbl + kAh) ^ xm;
                uint32_t koB  = (kbl + kBh) ^ xm;
                uint32_t ah[4][4], al[4][4], bh[4][2], bl[4][2];
#pragma unroll
                for (int mt = 0; mt < 4; mt++) {
                    uint32_t ad = sOff + aByte + mt * 2048;
                    LDSM_X4(ah[mt][0], ah[mt][1], ah[mt][2], ah[mt][3], bAh + ad + koA);
                    LDSM_X4(al[mt][0], al[mt][1], al[mt][2], al[mt][3], bAl + ad + koA);
                }
#pragma unroll
                for (int p = 0; p < 2; p++) {
                    uint32_t bd = sOff + bByte + p * 2048;
                    LDSM_X4(bh[2*p][0], bh[2*p][1], bh[2*p+1][0], bh[2*p+1][1], bBh + bd + koB);
                    LDSM_X4(bl[2*p][0], bl[2*p][1], bl[2*p+1][0], bl[2*p+1][1], bBl + bd + koB);
                }
#pragma unroll
                for (int mt = 0; mt < 4; mt++)
#pragma unroll
                    for (int nt = 0; nt < 4; nt++) {
                        MMA16816(acc[mt][nt], ah[mt], bh[nt]);
                        MMA16816(acc[mt][nt], ah[mt], bl[nt]);
                        MMA16816(acc[mt][nt], al[mt], bh[nt]);
                    }
            }
            __syncthreads();   // compute done before restaging / next job
        }

        // ---- epilogue: fold accumulators to per-anchor min/max ----
        int l4 = lane >> 2, lm = lane & 3;
        int gjc[8];
#pragma unroll
        for (int nt = 0; nt < 4; nt++) {
            int c0 = wn * 32 + nt * 8 + 2 * lm;
            gjc[2*nt]     = sB[c0];
            gjc[2*nt + 1] = sB[c0 + 1];
        }
#pragma unroll
        for (int mt = 0; mt < 4; mt++) {
            int r1 = wm * 64 + mt * 16 + l4;
            int r2 = r1 + 8;
            int gi1 = sA[r1], gi2 = sA[r2];
            float v1 = isPos ? 1e9f : -1e9f;
            float v2 = v1;
#pragma unroll
            for (int nt = 0; nt < 4; nt++) {
                float d0 = acc[mt][nt][0], d1 = acc[mt][nt][1];
                float d2 = acc[mt][nt][2], d3 = acc[mt][nt][3];
                int j0 = gjc[2*nt], j1 = gjc[2*nt + 1];
                if (isPos) {
                    if (j0 >= 0 && j0 != gi1) v1 = fminf(v1, d0);
                    if (j1 >= 0 && j1 != gi1) v1 = fminf(v1, d1);
                    if (j0 >= 0 && j0 != gi2) v2 = fminf(v2, d2);
                    if (j1 >= 0 && j1 != gi2) v2 = fminf(v2, d3);
                } else {
                    if (j0 >= 0) { v1 = fmaxf(v1, d0); v2 = fmaxf(v2, d2); }
                    if (j1 >= 0) { v1 = fmaxf(v1, d1); v2 = fmaxf(v2, d3); }
                }
            }
#pragma unroll
            for (int o = 1; o <= 2; o <<= 1) {
                float o1 = __shfl_xor_sync(0xffffffffu, v1, o);
                float o2 = __shfl_xor_sync(0xffffffffu, v2, o);
                v1 = isPos ? fminf(v1, o1) : fmaxf(v1, o1);
                v2 = isPos ? fminf(v2, o2) : fmaxf(v2, o2);
            }
            if (lm == 0) {
                if (isPos) {
                    if (gi1 >= 0) atomicMin(&g_posmin[gi1], enc_f(v1));
                    if (gi2 >= 0) atomicMin(&g_posmin[gi2], enc_f(v2));
                } else {
                    if (gi1 >= 0) atomicMax(&g_negmax[gi1], enc_f(v1));
                    if (gi2 >= 0) atomicMax(&g_negmax[gi2], enc_f(v2));
                }
            }
        }
        __syncthreads();   // protect sA/sB/smem before next job
    }
}

// ---- K4: per-anchor triplet + deterministic reduction ----
__global__ void k_finalreduce(const void* __restrict__ labv, int N,
                              float* __restrict__ out) {
    __shared__ float ssum[512];
    __shared__ int   snum[512];
    int tid = threadIdx.x;
    float s = 0.0f;
    int   n = 0;
    for (int i = tid; i < N; i += 512) {
        long long l = g_lab64 ? reinterpret_cast<const long long*>(labv)[i]
                              : (long long)reinterpret_cast<const int*>(labv)[i];
        if (l >= 1 && l <= 6) {
            int c = (int)l - 1;
            if (g_cnt[c] >= 2 && g_cnt[c ^ 1] >= 1) {
                float hp = dec_f(g_posmin[i]);
                float hn = dec_f(g_negmax[i]);
                s += fmaxf(0.0f, 0.5f + hn - hp);
                n++;
            }
        }
    }
    ssum[tid] = s; snum[tid] = n;
    __syncthreads();
    for (int o = 256; o; o >>= 1) {
        if (tid < o) { ssum[tid] += ssum[tid + o]; snum[tid] += snum[tid + o]; }
        __syncthreads();
    }
    if (tid == 0) out[0] = (snum[0] > 0) ? ssum[0] / (float)snum[0] : 0.0f;
}

extern "C" void kernel_launch(void* const* d_in, const int* in_sizes, int n_in,
                              void* d_out, int out_size) {
    const float* emb = (const float*)d_in[0];
    const void*  lab = d_in[1];
    int N = in_sizes[1];
    if (N > NMAX) N = NMAX;

    cudaFuncSetAttribute(k_main, cudaFuncAttributeMaxDynamicSharedMemorySize, DSMEM);

    k_zero<<<1, 32>>>((const long long*)lab, N);
    k_norm<<<(N + 7) / 8, 256>>>(emb, N);
    k_compact<<<(N + 255) / 256, 256>>>(lab, N);
    k_main<<<148, 256, DSMEM>>>();
    k_finalreduce<<<1, 512>>>(lab, N, (float*)d_out);
}

// round 8
// speedup vs baseline: 3.3902x; 1.7809x over previous
#include <cuda_runtime.h>
#include <cuda_bf16.h>
#include <cstdint>

#define H      256
#define NMAX   8192
#define NCLS   6        // classes 1..6; confused pair of c is c^1 (0-based)
#define TAJ    128      // anchors per job (M)
#define TBJ    128      // cols per job (N)
#define KCH    64       // K elements per staged chunk
#define NCH    4        // chunks per job
#define MAT_B  16384    // bytes per matrix per chunk: 128 rows x 64 bf16 x 2B
#define BUF_B  (4 * MAT_B)          // Ah,Al,Bh,Bl = 64 KB
#define DSMEM  (2 * BUF_B + 1024)   // double-buffered + align slack

// ---- scratch (static device globals; no dynamic allocation) ----
__device__ __nv_bfloat16 g_eh[NMAX * H];   // hi bf16 of normalized embeddings
__device__ __nv_bfloat16 g_el[NMAX * H];   // lo residual bf16
__device__ int      g_idx[NCLS][NMAX];
__device__ int      g_cnt[NCLS];
__device__ unsigned g_posmin[NMAX];
__device__ unsigned g_negmax[NMAX];
__device__ int      g_lab64;
__device__ int      g_ticket;

__device__ __forceinline__ unsigned enc_f(float f) {
    unsigned u = __float_as_uint(f);
    return (u & 0x80000000u) ? ~u : (u | 0x80000000u);
}
__device__ __forceinline__ float dec_f(unsigned v) {
    return __uint_as_float((v & 0x80000000u) ? (v ^ 0x80000000u) : ~v);
}
__device__ __forceinline__ uint32_t smem_u32(const void* p) {
    uint32_t a;
    asm("{ .reg .u64 t; cvta.to.shared.u64 t, %1; cvt.u32.u64 %0, t; }" : "=r"(a) : "l"(p));
    return a;
}

#define LDSM_X4(r0, r1, r2, r3, addr) \
    asm volatile("ldmatrix.sync.aligned.m8n8.x4.shared.b16 {%0,%1,%2,%3}, [%4];" \
        : "=r"(r0), "=r"(r1), "=r"(r2), "=r"(r3) : "r"(addr))

#define MMA16816(d, a, b) \
    asm volatile("mma.sync.aligned.m16n8k16.row.col.f32.bf16.bf16.f32 " \
        "{%0,%1,%2,%3}, {%4,%5,%6,%7}, {%8,%9}, {%0,%1,%2,%3};" \
        : "+f"((d)[0]), "+f"((d)[1]), "+f"((d)[2]), "+f"((d)[3]) \
        : "r"((a)[0]), "r"((a)[1]), "r"((a)[2]), "r"((a)[3]), \
          "r"((b)[0]), "r"((b)[1]))

#define CP_ASYNC16(dst, src, srcsize) \
    asm volatile("cp.async.cg.shared.global [%0], [%1], 16, %2;" \
        :: "r"(dst), "l"(src), "r"(srcsize) : "memory")
#define CP_COMMIT()  asm volatile("cp.async.commit_group;" ::: "memory")
#define CP_WAIT(n)   asm volatile("cp.async.wait_group %0;" :: "n"(n) : "memory")

// ---- K0: zero counters + ticket, detect label dtype ----
__global__ void k_zero(const long long* __restrict__ lab, int N) {
    int t = threadIdx.x;
    if (t < NCLS) g_cnt[t] = 0;
    if (t == 30) g_ticket = 0;
    if (t == 31) {
        int n = (N < 16) ? N : 16;
        int ok = 1;
        for (int i = 0; i < n; i++) {
            long long v = lab[i];
            if (v < -1000000LL || v > 1000000LL) ok = 0;
        }
        g_lab64 = ok;
    }
}

// ---- K1: L2-normalize rows, emit bf16 hi/lo split, init min/max ----
__global__ void k_norm(const float* __restrict__ emb, int N) {
    int row  = blockIdx.x * 8 + (threadIdx.x >> 5);
    int lane = threadIdx.x & 31;
    if (row >= N) return;
    const float4* src = reinterpret_cast<const float4*>(emb) + row * (H / 4);
    float4 v0 = src[lane * 2];
    float4 v1 = src[lane * 2 + 1];
    float ss = v0.x*v0.x + v0.y*v0.y + v0.z*v0.z + v0.w*v0.w
             + v1.x*v1.x + v1.y*v1.y + v1.z*v1.z + v1.w*v1.w;
#pragma unroll
    for (int o = 16; o; o >>= 1) ss += __shfl_xor_sync(0xffffffffu, ss, o);
    float s = 1.0f / fmaxf(sqrtf(ss), 1e-12f);
    float f[8] = { v0.x*s, v0.y*s, v0.z*s, v0.w*s, v1.x*s, v1.y*s, v1.z*s, v1.w*s };
    unsigned hw[4], lw[4];
#pragma unroll
    for (int p = 0; p < 4; p++) {
        float a = f[2*p], b = f[2*p+1];
        __nv_bfloat16 ha = __float2bfloat16_rn(a);
        __nv_bfloat16 hb = __float2bfloat16_rn(b);
        __nv_bfloat16 la = __float2bfloat16_rn(a - __bfloat162float(ha));
        __nv_bfloat16 lb = __float2bfloat16_rn(b - __bfloat162float(hb));
        hw[p] = (unsigned)__bfloat16_as_ushort(ha) | ((unsigned)__bfloat16_as_ushort(hb) << 16);
        lw[p] = (unsigned)__bfloat16_as_ushort(la) | ((unsigned)__bfloat16_as_ushort(lb) << 16);
    }
    reinterpret_cast<uint4*>(g_eh)[row * (H / 8) + lane] = make_uint4(hw[0], hw[1], hw[2], hw[3]);
    reinterpret_cast<uint4*>(g_el)[row * (H / 8) + lane] = make_uint4(lw[0], lw[1], lw[2], lw[3]);
    if (lane == 0) {
        g_posmin[row] = enc_f(1e9f);
        g_negmax[row] = enc_f(-1e9f);
    }
}

// ---- K2: compact row indices per class, block-aggregated atomics ----
__global__ void k_compact(const void* __restrict__ labv, int N) {
    __shared__ int hcnt[NCLS];
    __shared__ int hbase[NCLS];
    int tid = threadIdx.x;
    if (tid < NCLS) hcnt[tid] = 0;
    __syncthreads();
    int i = blockIdx.x * 256 + tid;
    int c = -1, p = 0;
    if (i < N) {
        long long l = g_lab64 ? reinterpret_cast<const long long*>(labv)[i]
                              : (long long)reinterpret_cast<const int*>(labv)[i];
        if (l >= 1 && l <= 6) {
            c = (int)l - 1;
            p = atomicAdd(&hcnt[c], 1);
        }
    }
    __syncthreads();
    if (tid < NCLS) hbase[tid] = hcnt[tid] ? atomicAdd(&g_cnt[tid], hcnt[tid]) : 0;
    __syncthreads();
    if (c >= 0) g_idx[c][hbase[c] + p] = i;
}

// ---- K3: persistent HMMA GEMM, cp.async double-buffered, 16 warps ----
// Job = (class c, 128-anchor tile, 128-col tile, pos/neg list).
// K in 4 chunks of 64; per chunk stage Ah/Al/Bh/Bl (16 KB each) via cp.async
// into alternating buffers while computing the previous chunk.
// Warp grid 4x4; each warp owns a 32x32 output tile (2x4 m16n8 tiles).
__global__ __launch_bounds__(512, 1) void k_main() {
    extern __shared__ char dsm_raw[];
    __shared__ int sA[TAJ], sB[TBJ];
    __shared__ int sjob, scnt[NCLS];

    int tid  = threadIdx.x;
    int wid  = tid >> 5;
    int lane = tid & 31;
    int wm   = wid >> 2;          // 0..3 (M: 32 rows each)
    int wn   = wid & 3;           // 0..3 (N: 32 cols each)

    unsigned dynaddr = smem_u32(dsm_raw);
    unsigned base0   = (dynaddr + 1023u) & ~1023u;

    if (tid < NCLS) scnt[tid] = g_cnt[tid];

    // per-lane ldmatrix address components (validated in R6)
    const uint32_t aRow = ((lane >> 3) & 1) * 8 + (lane & 7);
    const uint32_t kAh  = ((lane >> 4) & 1) * 16;
    const uint32_t bRow = ((lane >> 4) & 1) * 8 + (lane & 7);
    const uint32_t kBh  = ((lane >> 3) & 1) * 16;
    const uint32_t xm   = (lane & 7) << 4;
    const uint32_t aByte = (wm * 32 + aRow) * 128;
    const uint32_t bByte = (wn * 32 + bRow) * 128;
    (void)bRow;

    // staging geometry: 8 cp.async per thread per chunk.
    // iteration it (0..7): matrix m = it>>1, row r = r0 + (it&1)*64,
    // 16B unit iu = tid&7. r0 = (tid>>3)&63.
    const int r0 = (tid >> 3) & 63;
    const int iu = tid & 7;
    const uint32_t dsw = (unsigned)(iu * 16);

    for (;;) {
        if (tid == 0) sjob = atomicAdd(&g_ticket, 1);
        __syncthreads();
        int rem = sjob;

        int c = -1, atile = 0, ct = 0, pt = 0;
#pragma unroll
        for (int cc = 0; cc < NCLS; cc++) {
            int at = (scnt[cc] + TAJ - 1) / TAJ;
            int p  = (scnt[cc] + TBJ - 1) / TBJ;
            int n  = (scnt[cc ^ 1] + TBJ - 1) / TBJ;
            int nj = at * (p + n);
            if (c < 0) {
                if (rem < nj) { c = cc; atile = rem / (p + n); ct = rem % (p + n); pt = p; }
                else rem -= nj;
            }
        }
        if (c < 0) break;

        bool isPos = (ct < pt);
        int lc     = isPos ? c : (c ^ 1);
        int cbase  = (isPos ? ct : ct - pt) * TBJ;
        int cntA = scnt[c], cntB = scnt[lc];

        if (tid < TAJ) { int a = atile * TAJ + tid; sA[tid] = (a < cntA) ? g_idx[c][a]  : -1; }
        else if (tid < TAJ + TBJ) {
            int j = cbase + (tid - TAJ);
            sB[tid - TAJ] = (j < cntB) ? g_idx[lc][j] : -1;
        }
        __syncthreads();

        // hoist per-thread staging sources (4 distinct rows: A r0, A r0+64, B r0, B r0+64)
        int ga0 = sA[r0], ga1 = sA[r0 + 64];
        int gb0 = sB[r0], gb1 = sB[r0 + 64];
        const char* srcs[8];
        unsigned    ssz[8];
        unsigned    dsts[8];
        {
            int gs[8] = { ga0, ga1, ga0, ga1, gb0, gb1, gb0, gb1 };
            const __nv_bfloat16* arr[8] = { g_eh, g_eh, g_el, g_el, g_eh, g_eh, g_el, g_el };
#pragma unroll
            for (int it = 0; it < 8; it++) {
                int g = gs[it];
                srcs[it] = reinterpret_cast<const char*>(arr[it] + (size_t)(g < 0 ? 0 : g) * H) + iu * 16;
                ssz[it]  = (g >= 0) ? 16u : 0u;
                int m = it >> 1;
                int r = r0 + (it & 1) * 64;
                dsts[it] = (unsigned)m * MAT_B + (unsigned)r * 128
                         + (dsw ^ (((unsigned)r & 7) << 4));
            }
        }

        float acc[2][4][4];
#pragma unroll
        for (int mt = 0; mt < 2; mt++)
#pragma unroll
            for (int nt = 0; nt < 4; nt++)
#pragma unroll
                for (int e = 0; e < 4; e++) acc[mt][nt][e] = 0.0f;

        // prologue: issue chunk 0
        {
            unsigned buf = base0;
#pragma unroll
            for (int it = 0; it < 8; it++)
                CP_ASYNC16(buf + dsts[it], srcs[it], ssz[it]);
            CP_COMMIT();
        }

#pragma unroll 1
        for (int ch = 0; ch < NCH; ch++) {
            if (ch + 1 < NCH) {
                unsigned buf = base0 + ((unsigned)(ch + 1) & 1u) * BUF_B;
                unsigned koff = (unsigned)(ch + 1) * (KCH * 2);  // byte advance in source row
#pragma unroll
                for (int it = 0; it < 8; it++)
                    CP_ASYNC16(buf + dsts[it], srcs[it] + koff, ssz[it]);
                CP_COMMIT();
                CP_WAIT(1);
            } else {
                CP_WAIT(0);
            }
            __syncthreads();

            unsigned bufc = base0 + ((unsigned)ch & 1u) * BUF_B;
            const uint32_t bAh = bufc;
            const uint32_t bAl = bufc + MAT_B;
            const uint32_t bBh = bufc + 2 * MAT_B;
            const uint32_t bBl = bufc + 3 * MAT_B;

#pragma unroll
            for (int kk = 0; kk < 4; kk++) {
                uint32_t kbl = (uint32_t)kk * 32;
                uint32_t koA = (kbl + kAh) ^ xm;
                uint32_t koB = (kbl + kBh) ^ xm;
                uint32_t ah[2][4], al[2][4], bh[4][2], bl[4][2];
#pragma unroll
                for (int mt = 0; mt < 2; mt++) {
                    uint32_t ad = aByte + mt * 2048;
                    LDSM_X4(ah[mt][0], ah[mt][1], ah[mt][2], ah[mt][3], bAh + ad + koA);
                    LDSM_X4(al[mt][0], al[mt][1], al[mt][2], al[mt][3], bAl + ad + koA);
                }
#pragma unroll
                for (int p = 0; p < 2; p++) {
                    uint32_t bd = bByte + p * 2048;
                    LDSM_X4(bh[2*p][0], bh[2*p][1], bh[2*p+1][0], bh[2*p+1][1], bBh + bd + koB);
                    LDSM_X4(bl[2*p][0], bl[2*p][1], bl[2*p+1][0], bl[2*p+1][1], bBl + bd + koB);
                }
#pragma unroll
                for (int mt = 0; mt < 2; mt++)
#pragma unroll
                    for (int nt = 0; nt < 4; nt++) {
                        MMA16816(acc[mt][nt], ah[mt], bh[nt]);
                        MMA16816(acc[mt][nt], ah[mt], bl[nt]);
                        MMA16816(acc[mt][nt], al[mt], bh[nt]);
                    }
            }
            __syncthreads();   // buffer consumed before reuse by chunk ch+2
        }

        // ---- epilogue: fold accumulators to per-anchor min/max ----
        int l4 = lane >> 2, lm = lane & 3;
        int gjc[8];
#pragma unroll
        for (int nt = 0; nt < 4; nt++) {
            int c0 = wn * 32 + nt * 8 + 2 * lm;
            gjc[2*nt]     = sB[c0];
            gjc[2*nt + 1] = sB[c0 + 1];
        }
#pragma unroll
        for (int mt = 0; mt < 2; mt++) {
            int r1 = wm * 32 + mt * 16 + l4;
            int r2 = r1 + 8;
            int gi1 = sA[r1], gi2 = sA[r2];
            float v1 = isPos ? 1e9f : -1e9f;
            float v2 = v1;
#pragma unroll
            for (int nt = 0; nt < 4; nt++) {
                float d0 = acc[mt][nt][0], d1 = acc[mt][nt][1];
                float d2 = acc[mt][nt][2], d3 = acc[mt][nt][3];
                int j0 = gjc[2*nt], j1 = gjc[2*nt + 1];
                if (isPos) {
                    if (j0 >= 0 && j0 != gi1) v1 = fminf(v1, d0);
                    if (j1 >= 0 && j1 != gi1) v1 = fminf(v1, d1);
                    if (j0 >= 0 && j0 != gi2) v2 = fminf(v2, d2);
                    if (j1 >= 0 && j1 != gi2) v2 = fminf(v2, d3);
                } else {
                    if (j0 >= 0) { v1 = fmaxf(v1, d0); v2 = fmaxf(v2, d2); }
                    if (j1 >= 0) { v1 = fmaxf(v1, d1); v2 = fmaxf(v2, d3); }
                }
            }
#pragma unroll
            for (int o = 1; o <= 2; o <<= 1) {
                float o1 = __shfl_xor_sync(0xffffffffu, v1, o);
                float o2 = __shfl_xor_sync(0xffffffffu, v2, o);
                v1 = isPos ? fminf(v1, o1) : fmaxf(v1, o1);
                v2 = isPos ? fminf(v2, o2) : fmaxf(v2, o2);
            }
            if (lm == 0) {
                if (isPos) {
                    if (gi1 >= 0) atomicMin(&g_posmin[gi1], enc_f(v1));
                    if (gi2 >= 0) atomicMin(&g_posmin[gi2], enc_f(v2));
                } else {
                    if (gi1 >= 0) atomicMax(&g_negmax[gi1], enc_f(v1));
                    if (gi2 >= 0) atomicMax(&g_negmax[gi2], enc_f(v2));
                }
            }
        }
        __syncthreads();   // protect sA/sB/smem before next job
    }
}

// ---- K4: per-anchor triplet + deterministic reduction ----
__global__ void k_finalreduce(const void* __restrict__ labv, int N,
                              float* __restrict__ out) {
    __shared__ float ssum[512];
    __shared__ int   snum[512];
    int tid = threadIdx.x;
    float s = 0.0f;
    int   n = 0;
    for (int i = tid; i < N; i += 512) {
        long long l = g_lab64 ? reinterpret_cast<const long long*>(labv)[i]
                              : (long long)reinterpret_cast<const int*>(labv)[i];
        if (l >= 1 && l <= 6) {
            int c = (int)l - 1;
            if (g_cnt[c] >= 2 && g_cnt[c ^ 1] >= 1) {
                float hp = dec_f(g_posmin[i]);
                float hn = dec_f(g_negmax[i]);
                s += fmaxf(0.0f, 0.5f + hn - hp);
                n++;
            }
        }
    }
    ssum[tid] = s; snum[tid] = n;
    __syncthreads();
    for (int o = 256; o; o >>= 1) {
        if (tid < o) { ssum[tid] += ssum[tid + o]; snum[tid] += snum[tid + o]; }
        __syncthreads();
    }
    if (tid == 0) out[0] = (snum[0] > 0) ? ssum[0] / (float)snum[0] : 0.0f;
}

extern "C" void kernel_launch(void* const* d_in, const int* in_sizes, int n_in,
                              void* d_out, int out_size) {
    const float* emb = (const float*)d_in[0];
    const void*  lab = d_in[1];
    int N = in_sizes[1];
    if (N > NMAX) N = NMAX;

    cudaFuncSetAttribute(k_main, cudaFuncAttributeMaxDynamicSharedMemorySize, DSMEM);

    k_zero<<<1, 32>>>((const long long*)lab, N);
    k_norm<<<(N + 7) / 8, 256>>>(emb, N);
    k_compact<<<(N + 255) / 256, 256>>>(lab, N);
    k_main<<<148, 512, DSMEM>>>();
    k_finalreduce<<<1, 512>>>(lab, N, (float*)d_out);
}